// round 14
// baseline (speedup 1.0000x reference)
#include <cuda_runtime.h>
#include <cuda_bf16.h>
#include <cstdint>

// ---------------- problem constants ----------------
#define B 8
#define H 16
#define DIM 2048
#define QLR 1536
#define KVLR 512
#define DN 128
#define DR 64
#define DV 128
#define T_TOT 8192
#define T_PREFIX 8191
#define NCHUNK 32          // partials per batch (one per CTA)
#define NCPC 16            // chunks per CTA
#define CHUNK 16           // tokens per chunk
#define DHEAD 576
#define KSTR 580           // fp32 row stride (≡4 mod 32 banks)
#define PSTR 20            // probs/score row stride (≡20 mod 32, conflict-free frags)
#define SCALEF 0.07216878364870322f

typedef unsigned long long u64;

// ---------------- device scratch ----------------
__device__ float g_qa  [B*QLR];
__device__ float g_kvpe[B*(KVLR+DR)];
__device__ float g_qan [B*QLR];
__device__ float g_kvn [B*KVLR];
__device__ float g_pen [B*DR];
__device__ float g_q   [B*H*(DN+DR)];
__device__ float g_qfull[B*H*DHEAD];
__device__ float g_pm  [B*NCHUNK*H];
__device__ float g_pl  [B*NCHUNK*H];
__device__ float g_pout[B*NCHUNK*H*KVLR];    // 8.4 MB
__device__ float g_out2[B*H*DV];

__device__ __forceinline__ uint32_t tf32_of(float f){
    uint32_t r; asm("cvt.rna.tf32.f32 %0, %1;" : "=r"(r) : "f"(f)); return r;
}
__device__ __forceinline__ uint32_t smem_u32(const void* p){
    uint32_t a;
    asm("{ .reg .u64 t; cvta.to.shared.u64 t, %1; cvt.u32.u64 %0, t; }" : "=r"(a) : "l"(p));
    return a;
}

// ========== K1: qa = x @ wq_a^T + b ; kvpe = x @ wkv_a^T + b ==========
__global__ void k_proj_a(const float* __restrict__ x,
                         const float* __restrict__ wqa, const float* __restrict__ bqa,
                         const float* __restrict__ wkva, const float* __restrict__ bkva){
    extern __shared__ float xs[];
    int tid = threadIdx.x;
    for (int i = tid; i < B*DIM; i += blockDim.x) xs[i] = x[i];
    __syncthreads();
    int warp = tid >> 5, lane = tid & 31;
    int r = blockIdx.x * 8 + warp;
    if (r >= QLR + KVLR + DR) return;
    const float* wrow; float bias;
    if (r < QLR) { wrow = wqa + (long)r*DIM; bias = bqa[r]; }
    else         { wrow = wkva + (long)(r-QLR)*DIM; bias = bkva[r-QLR]; }
    float w[64];
    #pragma unroll
    for (int k = 0; k < 64; k++) w[k] = wrow[lane + 32*k];
    for (int b = 0; b < B; b++){
        const float* xb = xs + b*DIM;
        float s = 0.f;
        #pragma unroll
        for (int k = 0; k < 64; k++) s += w[k]*xb[lane + 32*k];
        #pragma unroll
        for (int o = 16; o; o >>= 1) s += __shfl_xor_sync(0xffffffffu, s, o);
        if (lane == 0){
            if (r < QLR) g_qa[b*QLR + r] = s + bias;
            else         g_kvpe[b*(KVLR+DR) + (r-QLR)] = s + bias;
        }
    }
}

// ========== K2: RMS-norm qa and kv; rope k_pe ==========
__global__ void k_norm_rope(const float* __restrict__ qnw, const float* __restrict__ kvnw,
                            const float* __restrict__ fcos, const float* __restrict__ fsin){
    int b = blockIdx.x, tid = threadIdx.x;
    __shared__ float red[16];
    __shared__ float sq, skv;
    float s = 0.f;
    for (int i = tid; i < QLR; i += 512){ float v = g_qa[b*QLR+i]; s += v*v; }
    #pragma unroll
    for (int o = 16; o; o >>= 1) s += __shfl_xor_sync(0xffffffffu, s, o);
    if ((tid&31) == 0) red[tid>>5] = s;
    __syncthreads();
    if (tid == 0){ float t=0; for (int i=0;i<16;i++) t += red[i];
                   sq = rsqrtf(t*(1.f/QLR) + 1e-6f); }
    __syncthreads();
    float s2 = 0.f;
    { float v = (tid < KVLR) ? g_kvpe[b*(KVLR+DR)+tid] : 0.f; s2 = v*v; }
    #pragma unroll
    for (int o = 16; o; o >>= 1) s2 += __shfl_xor_sync(0xffffffffu, s2, o);
    if ((tid&31) == 0) red[tid>>5] = s2;
    __syncthreads();
    if (tid == 0){ float t=0; for (int i=0;i<16;i++) t += red[i];
                   skv = rsqrtf(t*(1.f/KVLR) + 1e-6f); }
    __syncthreads();
    for (int i = tid; i < QLR; i += 512) g_qan[b*QLR+i] = g_qa[b*QLR+i]*qnw[i]*sq;
    if (tid < KVLR) g_kvn[b*KVLR+tid] = g_kvpe[b*(KVLR+DR)+tid]*kvnw[tid]*skv;
    if (tid < DR){
        int i = tid >> 1;
        float xr = g_kvpe[b*(KVLR+DR)+KVLR+2*i];
        float xi = g_kvpe[b*(KVLR+DR)+KVLR+2*i+1];
        float c = fcos[i], sn = fsin[i];
        g_pen[b*DR+tid] = (tid&1) ? (xr*sn + xi*c) : (xr*c - xi*sn);
    }
}

// ========== K3: q = qa_n @ wq_b^T + b ==========
__global__ void k_proj_qb(const float* __restrict__ wqb, const float* __restrict__ bqb){
    extern __shared__ float qs[];
    int tid = threadIdx.x;
    for (int i = tid; i < B*QLR; i += blockDim.x) qs[i] = g_qan[i];
    __syncthreads();
    int warp = tid >> 5, lane = tid & 31;
    int r = blockIdx.x * 8 + warp;
    const float* wr = wqb + (long)r*QLR;
    float w[48];
    #pragma unroll
    for (int k = 0; k < 48; k++) w[k] = wr[lane + 32*k];
    float bias = bqb[r];
    for (int b = 0; b < B; b++){
        const float* xb = qs + b*QLR;
        float s = 0.f;
        #pragma unroll
        for (int k = 0; k < 48; k++) s += w[k]*xb[lane + 32*k];
        #pragma unroll
        for (int o = 16; o; o >>= 1) s += __shfl_xor_sync(0xffffffffu, s, o);
        if (lane == 0) g_q[b*(H*(DN+DR)) + r] = s + bias;
    }
}

// ========== K4: q_full = [q_nope @ wkv_b[:, :DN], rope(q_pe)] ==========
// grid (H, 9), 512 threads. parts 0-7: 64-col slice; 8 d-groups of 16, MLP=16.
__global__ void k_qfull(const float* __restrict__ wkvb,
                        const float* __restrict__ fcos, const float* __restrict__ fsin){
    int h = blockIdx.x, part = blockIdx.y, tid = threadIdx.x;
    if (part < 8){
        __shared__ float qn[B][DN];
        __shared__ float red[8][B][65];
        for (int i = tid; i < B*DN; i += 512){ int b = i>>7, d = i&127;
            qn[b][d] = g_q[b*(H*(DN+DR)) + h*(DN+DR) + d]; }
        __syncthreads();
        int dg = tid >> 6, cc = tid & 63;
        int c = part*64 + cc;
        const float* wp = wkvb + (long)(h*(DN+DV) + dg*16)*KVLR + c;
        float w[16];
        #pragma unroll
        for (int ds = 0; ds < 16; ds++) w[ds] = wp[(long)ds*KVLR];
        float acc[B];
        #pragma unroll
        for (int b = 0; b < B; b++) acc[b] = 0.f;
        #pragma unroll
        for (int ds = 0; ds < 16; ds++){
            #pragma unroll
            for (int b = 0; b < B; b++)
                acc[b] += qn[b][dg*16 + ds]*w[ds];
        }
        #pragma unroll
        for (int b = 0; b < B; b++) red[dg][b][cc] = acc[b];
        __syncthreads();
        for (int i = tid; i < B*64; i += 512){
            int b = i >> 6, c2 = i & 63;
            float s = 0.f;
            #pragma unroll
            for (int d = 0; d < 8; d++) s += red[d][b][c2];
            g_qfull[(b*H + h)*DHEAD + part*64 + c2] = s;
        }
    } else {
        if (tid < DR){
            int i = tid >> 1;
            float c = fcos[i], sn = fsin[i];
            for (int b = 0; b < B; b++){
                float xr = g_q[b*(H*(DN+DR)) + h*(DN+DR) + DN + 2*i];
                float xi = g_q[b*(H*(DN+DR)) + h*(DN+DR) + DN + 2*i + 1];
                g_qfull[(b*H + h)*DHEAD + KVLR + tid] =
                    (tid&1) ? (xr*sn + xi*c) : (xr*c - xi*sn);
            }
        }
    }
}

// ========== K5: persistent split-K attention, 2 CTAs/SM ==========
// grid (32, 8), 256 threads (8 warps). Each CTA: 16 chunks x 16 tokens,
// online softmax, cp.async double-buffered kv, tf32 MMA both GEMMs,
// Q fragments loaded from global to registers (no Q smem).
//
// smem floats: kv0 [16*580]=9280 | kv1 9280 | pr [4][16][20]=1280 | ps [16][20]=320 | s_c 16
#define SMF_KV0 0
#define SMF_KV1 9280
#define SMF_PR  18560
#define SMF_PS  19840
#define SMF_SC  20160
#define SM_TOTAL ((20160 + 16)*4)   // 80704 bytes

__device__ __forceinline__ void issue_chunk(
    const float* __restrict__ kvp, const float* __restrict__ pep,
    int b, int t0, uint32_t dstbase, const int* tk, const int* jk){
    #pragma unroll
    for (int k = 0; k < 9; k++){
        int tg = t0 + tk[k];
        int j = jk[k];
        const char* src;
        if (tg == T_PREFIX)
            src = (j < 128) ? (const char*)(g_kvn + b*KVLR) + j*16
                            : (const char*)(g_pen + b*DR) + (j-128)*16;
        else
            src = (j < 128) ? (const char*)(kvp + ((long)b*T_PREFIX + tg)*KVLR) + j*16
                            : (const char*)(pep + ((long)b*T_PREFIX + tg)*DR) + (j-128)*16;
        uint32_t dst = dstbase + (uint32_t)(tk[k]*2320 + j*16);
        asm volatile("cp.async.cg.shared.global [%0], [%1], 16;" :: "r"(dst), "l"(src));
    }
    asm volatile("cp.async.commit_group;" ::: "memory");
}

__global__ void __launch_bounds__(256, 2) k_attn(const float* __restrict__ kvp,
                                                 const float* __restrict__ pep){
    extern __shared__ float smf[];
    float* pr  = smf + SMF_PR;    // [4][16][20]
    float* ps  = smf + SMF_PS;    // [16][20]
    float* s_c = smf + SMF_SC;    // [16]
    int g = blockIdx.x, b = blockIdx.y, tid = threadIdx.x;
    int warp = tid >> 5, lane = tid & 31;
    int l4 = lane >> 2, lm4 = lane & 3;
    uint32_t sb = smem_u32(smf);

    int tk[9], jk[9];
    #pragma unroll
    for (int k = 0; k < 9; k++){ int idx = tid + 256*k; tk[k] = idx/144; jk[k] = idx%144; }

    // kick off chunk 0
    issue_chunk(kvp, pep, b, g*NCPC*CHUNK, sb + SMF_KV0*4, tk, jk);

    // Q tf32 fragments straight from global (latency hidden behind chunk-0 copy)
    int tile_n = warp & 1, kh = warp >> 1;      // 2 n-tiles x 4 k-splits
    uint32_t qf0[18], qf1[18];
    {
        const float* qr = g_qfull + (long)(b*H + tile_n*8 + l4)*DHEAD + kh*144 + lm4;
        #pragma unroll
        for (int kc = 0; kc < 18; kc++){
            qf0[kc] = tf32_of(qr[kc*8]);
            qf1[kc] = tf32_of(qr[kc*8 + 4]);
        }
    }

    float m_run = -1e30f, l_run = 0.f;
    float acc[8][4];
    #pragma unroll
    for (int nt = 0; nt < 8; nt++)
        #pragma unroll
        for (int j = 0; j < 4; j++) acc[nt][j] = 0.f;

    for (int i = 0; i < NCPC; i++){
        asm volatile("cp.async.wait_group 0;" ::: "memory");
        __syncthreads();                        // (A) copy visible; prev accumulate done
        const float* kvs = smf + ((i&1) ? SMF_KV1 : SMF_KV0);
        if (i + 1 < NCPC)
            issue_chunk(kvp, pep, b, (g*NCPC + i + 1)*CHUNK,
                        sb + (((i+1)&1) ? SMF_KV1 : SMF_KV0)*4, tk, jk);

        // ---- scores: m16(tokens) x n8(heads) x 4 k-split; Q frags in regs ----
        {
            const float* arow0 = kvs + l4*KSTR + kh*144 + lm4;
            const float* arow1 = arow0 + 8*KSTR;
            float d0 = 0.f, d1 = 0.f, d2 = 0.f, d3 = 0.f;
            #pragma unroll
            for (int kc = 0; kc < 18; kc++){
                uint32_t a0 = tf32_of(arow0[kc*8]);
                uint32_t a1 = tf32_of(arow1[kc*8]);
                uint32_t a2 = tf32_of(arow0[kc*8 + 4]);
                uint32_t a3 = tf32_of(arow1[kc*8 + 4]);
                asm volatile("mma.sync.aligned.m16n8k8.row.col.f32.tf32.tf32.f32 "
                    "{%0,%1,%2,%3}, {%4,%5,%6,%7}, {%8,%9}, {%0,%1,%2,%3};"
                    : "+f"(d0),"+f"(d1),"+f"(d2),"+f"(d3)
                    : "r"(a0),"r"(a1),"r"(a2),"r"(a3), "r"(qf0[kc]),"r"(qf1[kc]));
            }
            int h0 = tile_n*8 + 2*lm4;
            float* prk = pr + kh*320;
            prk[h0*PSTR + l4]           = d0;
            prk[(h0+1)*PSTR + l4]       = d1;
            prk[h0*PSTR + l4 + 8]       = d2;
            prk[(h0+1)*PSTR + l4 + 8]   = d3;
        }
        __syncthreads();                        // (B)

        // ---- online softmax: warp handles heads 2w, 2w+1 (16 lanes each) ----
        {
            int h = warp*2 + (lane >> 4);
            int t = lane & 15;
            float v = (pr[h*PSTR + t] + pr[320 + h*PSTR + t]
                     + pr[640 + h*PSTR + t] + pr[960 + h*PSTR + t]) * SCALEF;
            float bm = v;
            #pragma unroll
            for (int o = 8; o; o >>= 1) bm = fmaxf(bm, __shfl_xor_sync(0xffffffffu, bm, o));
            float mn = fmaxf(m_run, bm);
            float corr = __expf(m_run - mn);
            float p = __expf(v - mn);
            float l = p;
            #pragma unroll
            for (int o = 8; o; o >>= 1) l += __shfl_xor_sync(0xffffffffu, l, o);
            l_run = l_run*corr + l;
            m_run = mn;
            ps[h*PSTR + t] = p;
            if (t == 0) s_c[h] = corr;
        }
        __syncthreads();                        // (C)

        // ---- accumulate tf32 MMA: out[16h][64c per warp] += P @ KV ----
        {
            int n0 = warp*64;
            float corr0 = s_c[l4], corr1 = s_c[l4+8];
            #pragma unroll
            for (int nt = 0; nt < 8; nt++){
                acc[nt][0] *= corr0; acc[nt][1] *= corr0;
                acc[nt][2] *= corr1; acc[nt][3] *= corr1;
            }
            #pragma unroll
            for (int ks = 0; ks < 2; ks++){
                int k0 = ks*8;
                uint32_t a0 = tf32_of(ps[l4*PSTR + k0 + lm4]);
                uint32_t a1 = tf32_of(ps[(l4+8)*PSTR + k0 + lm4]);
                uint32_t a2 = tf32_of(ps[l4*PSTR + k0 + 4 + lm4]);
                uint32_t a3 = tf32_of(ps[(l4+8)*PSTR + k0 + 4 + lm4]);
                #pragma unroll
                for (int nt = 0; nt < 8; nt++){
                    int cn = n0 + nt*8 + l4;
                    uint32_t b0 = tf32_of(kvs[(k0 + lm4)*KSTR + cn]);
                    uint32_t b1 = tf32_of(kvs[(k0 + 4 + lm4)*KSTR + cn]);
                    asm volatile("mma.sync.aligned.m16n8k8.row.col.f32.tf32.tf32.f32 "
                        "{%0,%1,%2,%3}, {%4,%5,%6,%7}, {%8,%9}, {%0,%1,%2,%3};"
                        : "+f"(acc[nt][0]),"+f"(acc[nt][1]),"+f"(acc[nt][2]),"+f"(acc[nt][3])
                        : "r"(a0),"r"(a1),"r"(a2),"r"(a3), "r"(b0),"r"(b1));
                }
            }
        }
    }

    // ---- writeout: one partial per CTA ----
    if ((lane & 15) == 0){
        int h = warp*2 + (lane >> 4);
        g_pm[(b*NCHUNK + g)*H + h] = m_run;
        g_pl[(b*NCHUNK + g)*H + h] = l_run;
    }
    {
        int n0 = warp*64;
        long base0 = ((long)(b*NCHUNK + g)*H + l4)*KVLR;
        long base1 = ((long)(b*NCHUNK + g)*H + l4 + 8)*KVLR;
        #pragma unroll
        for (int nt = 0; nt < 8; nt++){
            int c = n0 + nt*8 + 2*lm4;
            *(float2*)(g_pout + base0 + c) = make_float2(acc[nt][0], acc[nt][1]);
            *(float2*)(g_pout + base1 + c) = make_float2(acc[nt][2], acc[nt][3]);
        }
    }
}

// ========== K6: combine split-softmax partials + V projection ==========
__global__ void k_reduce(const float* __restrict__ wkvb){
    int h = blockIdx.x, b = blockIdx.y, tid = threadIdx.x;
    __shared__ float sm_m[NCHUNK], sm_l[NCHUNK], wk[NCHUNK];
    __shared__ float so[KVLR];
    if (tid < NCHUNK){
        sm_m[tid] = g_pm[(b*NCHUNK + tid)*H + h];
        sm_l[tid] = g_pl[(b*NCHUNK + tid)*H + h];
    }
    __syncthreads();
    if (tid < 32){
        float mv = sm_m[tid];
        float M = mv;
        #pragma unroll
        for (int o = 16; o; o >>= 1) M = fmaxf(M, __shfl_xor_sync(0xffffffffu, M, o));
        float e = __expf(mv - M);
        float L = e*sm_l[tid];
        #pragma unroll
        for (int o = 16; o; o >>= 1) L += __shfl_xor_sync(0xffffffffu, L, o);
        wk[tid] = e / L;
    }
    __syncthreads();
    float out = 0.f;
    #pragma unroll 4
    for (int k = 0; k < NCHUNK; k++)
        out += wk[k]*g_pout[((long)(b*NCHUNK + k)*H + h)*KVLR + tid];
    so[tid] = out;
    __syncthreads();
    int d = tid >> 2, part = tid & 3;
    const float* wr = wkvb + (long)(h*(DN+DV) + DN + d)*KVLR + part*128;
    const float* sp = so + part*128;
    float s = 0.f;
    #pragma unroll 8
    for (int c = 0; c < 128; c++) s += sp[c]*wr[c];
    s += __shfl_xor_sync(0xffffffffu, s, 1);
    s += __shfl_xor_sync(0xffffffffu, s, 2);
    if (part == 0) g_out2[(b*H + h)*DV + d] = s;
}

// ========== K7: y = out2 @ wo^T + wo_b ==========
__global__ void k_proj_o(const float* __restrict__ wo, const float* __restrict__ wob,
                         float* __restrict__ out){
    extern __shared__ float xs[];
    int tid = threadIdx.x;
    for (int i = tid; i < B*DIM; i += blockDim.x) xs[i] = g_out2[i];
    __syncthreads();
    int warp = tid >> 5, lane = tid & 31;
    int j = blockIdx.x * 8 + warp;
    const float* wr = wo + (long)j*DIM;
    float w[64];
    #pragma unroll
    for (int k = 0; k < 64; k++) w[k] = wr[lane + 32*k];
    float bias = wob[j];
    for (int b = 0; b < B; b++){
        const float* xb = xs + b*DIM;
        float s = 0.f;
        #pragma unroll
        for (int k = 0; k < 64; k++) s += w[k]*xb[lane + 32*k];
        #pragma unroll
        for (int o = 16; o; o >>= 1) s += __shfl_xor_sync(0xffffffffu, s, o);
        if (lane == 0) out[b*DIM + j] = s + bias;
    }
}

// ---------------- host launcher ----------------
extern "C" void kernel_launch(void* const* d_in, const int* in_sizes, int n_in,
                              void* d_out, int out_size){
    const float* x    = (const float*)d_in[0];
    const float* fcos = (const float*)d_in[2];
    const float* fsin = (const float*)d_in[3];
    const float* kvp  = (const float*)d_in[4];
    const float* pep  = (const float*)d_in[5];
    const float* wqa  = (const float*)d_in[6];
    const float* bqa  = (const float*)d_in[7];
    const float* qnw  = (const float*)d_in[8];
    const float* wqb  = (const float*)d_in[9];
    const float* bqb  = (const float*)d_in[10];
    const float* wkva = (const float*)d_in[11];
    const float* bkva = (const float*)d_in[12];
    const float* kvnw = (const float*)d_in[13];
    const float* wkvb = (const float*)d_in[14];
    const float* wo   = (const float*)d_in[15];
    const float* wob  = (const float*)d_in[16];
    float* out = (float*)d_out;

    const int SMEM_K1 = B*DIM*4;
    const int SMEM_K3 = B*QLR*4;
    const int SMEM_K7 = B*DIM*4;
    cudaFuncSetAttribute(k_proj_a,  cudaFuncAttributeMaxDynamicSharedMemorySize, SMEM_K1);
    cudaFuncSetAttribute(k_proj_qb, cudaFuncAttributeMaxDynamicSharedMemorySize, SMEM_K3);
    cudaFuncSetAttribute(k_attn,    cudaFuncAttributeMaxDynamicSharedMemorySize, SM_TOTAL);
    cudaFuncSetAttribute(k_proj_o,  cudaFuncAttributeMaxDynamicSharedMemorySize, SMEM_K7);

    k_proj_a<<<(QLR+KVLR+DR)/8, 256, SMEM_K1>>>(x, wqa, bqa, wkva, bkva);
    k_norm_rope<<<B, 512>>>(qnw, kvnw, fcos, fsin);
    k_proj_qb<<<(H*(DN+DR))/8, 256, SMEM_K3>>>(wqb, bqb);
    { dim3 g(H, 9); k_qfull<<<g, 512>>>(wkvb, fcos, fsin); }
    { dim3 g(NCHUNK, B); k_attn<<<g, 256, SM_TOTAL>>>(kvp, pep); }
    { dim3 g(H, B); k_reduce<<<g, 512>>>(wkvb); }
    k_proj_o<<<DIM/8, 256, SMEM_K7>>>(wo, wob, out);
}

// round 15
// speedup vs baseline: 1.0985x; 1.0985x over previous
#include <cuda_runtime.h>
#include <cuda_bf16.h>
#include <cstdint>

// ---------------- problem constants ----------------
#define B 8
#define H 16
#define DIM 2048
#define QLR 1536
#define KVLR 512
#define DN 128
#define DR 64
#define DV 128
#define T_TOT 8192
#define T_PREFIX 8191
#define NCHUNK 16          // one partial per CTA
#define NCPC 16            // chunks per CTA
#define CHUNK 32           // tokens per chunk
#define DHEAD 576
#define KSTR 580           // fp32 row stride (≡4 mod 32 banks -> conflict-free frags)
#define PSTR 36            // probs row stride (≡4 mod 32)
#define SCALEF 0.07216878364870322f

typedef unsigned long long u64;

// ---------------- device scratch ----------------
__device__ float g_qa  [B*QLR];
__device__ float g_kvpe[B*(KVLR+DR)];
__device__ float g_qan [B*QLR];
__device__ float g_kvn [B*KVLR];
__device__ float g_pen [B*DR];
__device__ float g_q   [B*H*(DN+DR)];
__device__ float g_qfull[B*H*DHEAD];
__device__ float g_pm  [B*NCHUNK*H];
__device__ float g_pl  [B*NCHUNK*H];
__device__ float g_pout[B*NCHUNK*H*KVLR];    // 4.2 MB
__device__ float g_out2[B*H*DV];

__device__ __forceinline__ uint32_t tf32_of(float f){
    uint32_t r; asm("cvt.rna.tf32.f32 %0, %1;" : "=r"(r) : "f"(f)); return r;
}
__device__ __forceinline__ uint32_t smem_u32(const void* p){
    uint32_t a;
    asm("{ .reg .u64 t; cvta.to.shared.u64 t, %1; cvt.u32.u64 %0, t; }" : "=r"(a) : "l"(p));
    return a;
}
__device__ __forceinline__ float dot4(float4 a, float4 b){
    return a.x*b.x + a.y*b.y + a.z*b.z + a.w*b.w;
}

// ========== K1: qa = x @ wq_a^T + b ; kvpe = x @ wkv_a^T + b ==========
// float4 weight + x loads (coalesced 512B/warp-step, LDS.128 conflict-free).
__global__ void k_proj_a(const float* __restrict__ x,
                         const float* __restrict__ wqa, const float* __restrict__ bqa,
                         const float* __restrict__ wkva, const float* __restrict__ bkva){
    extern __shared__ float xs[];
    int tid = threadIdx.x;
    for (int i = tid; i < B*DIM/4; i += blockDim.x)
        ((float4*)xs)[i] = ((const float4*)x)[i];
    __syncthreads();
    int warp = tid >> 5, lane = tid & 31;
    int r = blockIdx.x * 8 + warp;
    if (r >= QLR + KVLR + DR) return;
    const float* wrow; float bias;
    if (r < QLR) { wrow = wqa + (long)r*DIM; bias = bqa[r]; }
    else         { wrow = wkva + (long)(r-QLR)*DIM; bias = bkva[r-QLR]; }
    float4 w[16];
    #pragma unroll
    for (int k = 0; k < 16; k++) w[k] = ((const float4*)wrow)[lane + 32*k];
    for (int b = 0; b < B; b++){
        const float4* xb = (const float4*)(xs + b*DIM);
        float s = 0.f;
        #pragma unroll
        for (int k = 0; k < 16; k++) s += dot4(w[k], xb[lane + 32*k]);
        #pragma unroll
        for (int o = 16; o; o >>= 1) s += __shfl_xor_sync(0xffffffffu, s, o);
        if (lane == 0){
            if (r < QLR) g_qa[b*QLR + r] = s + bias;
            else         g_kvpe[b*(KVLR+DR) + (r-QLR)] = s + bias;
        }
    }
}

// ========== K2: RMS-norm qa and kv; rope k_pe ==========
__global__ void k_norm_rope(const float* __restrict__ qnw, const float* __restrict__ kvnw,
                            const float* __restrict__ fcos, const float* __restrict__ fsin){
    int b = blockIdx.x, tid = threadIdx.x;
    __shared__ float red[16];
    __shared__ float sq, skv;
    float s = 0.f;
    for (int i = tid; i < QLR; i += 512){ float v = g_qa[b*QLR+i]; s += v*v; }
    #pragma unroll
    for (int o = 16; o; o >>= 1) s += __shfl_xor_sync(0xffffffffu, s, o);
    if ((tid&31) == 0) red[tid>>5] = s;
    __syncthreads();
    if (tid == 0){ float t=0; for (int i=0;i<16;i++) t += red[i];
                   sq = rsqrtf(t*(1.f/QLR) + 1e-6f); }
    __syncthreads();
    float s2 = 0.f;
    { float v = (tid < KVLR) ? g_kvpe[b*(KVLR+DR)+tid] : 0.f; s2 = v*v; }
    #pragma unroll
    for (int o = 16; o; o >>= 1) s2 += __shfl_xor_sync(0xffffffffu, s2, o);
    if ((tid&31) == 0) red[tid>>5] = s2;
    __syncthreads();
    if (tid == 0){ float t=0; for (int i=0;i<16;i++) t += red[i];
                   skv = rsqrtf(t*(1.f/KVLR) + 1e-6f); }
    __syncthreads();
    for (int i = tid; i < QLR; i += 512) g_qan[b*QLR+i] = g_qa[b*QLR+i]*qnw[i]*sq;
    if (tid < KVLR) g_kvn[b*KVLR+tid] = g_kvpe[b*(KVLR+DR)+tid]*kvnw[tid]*skv;
    if (tid < DR){
        int i = tid >> 1;
        float xr = g_kvpe[b*(KVLR+DR)+KVLR+2*i];
        float xi = g_kvpe[b*(KVLR+DR)+KVLR+2*i+1];
        float c = fcos[i], sn = fsin[i];
        g_pen[b*DR+tid] = (tid&1) ? (xr*sn + xi*c) : (xr*c - xi*sn);
    }
}

// ========== K3: q = qa_n @ wq_b^T + b ==========
__global__ void k_proj_qb(const float* __restrict__ wqb, const float* __restrict__ bqb){
    extern __shared__ float qs[];
    int tid = threadIdx.x;
    for (int i = tid; i < B*QLR/4; i += blockDim.x)
        ((float4*)qs)[i] = ((const float4*)g_qan)[i];
    __syncthreads();
    int warp = tid >> 5, lane = tid & 31;
    int r = blockIdx.x * 8 + warp;
    const float* wr = wqb + (long)r*QLR;
    float4 w[12];
    #pragma unroll
    for (int k = 0; k < 12; k++) w[k] = ((const float4*)wr)[lane + 32*k];
    float bias = bqb[r];
    for (int b = 0; b < B; b++){
        const float4* xb = (const float4*)(qs + b*QLR);
        float s = 0.f;
        #pragma unroll
        for (int k = 0; k < 12; k++) s += dot4(w[k], xb[lane + 32*k]);
        #pragma unroll
        for (int o = 16; o; o >>= 1) s += __shfl_xor_sync(0xffffffffu, s, o);
        if (lane == 0) g_q[b*(H*(DN+DR)) + r] = s + bias;
    }
}

// ========== K4: q_full = [q_nope @ wkv_b[:, :DN], rope(q_pe)] ==========
// grid (H, 9), 512 threads. parts 0-7: 64-col slice; 8 d-groups of 16. (R11 version)
__global__ void k_qfull(const float* __restrict__ wkvb,
                        const float* __restrict__ fcos, const float* __restrict__ fsin){
    int h = blockIdx.x, part = blockIdx.y, tid = threadIdx.x;
    if (part < 8){
        __shared__ float qn[B][DN];
        __shared__ float red[8][B][65];
        for (int i = tid; i < B*DN; i += 512){ int b = i>>7, d = i&127;
            qn[b][d] = g_q[b*(H*(DN+DR)) + h*(DN+DR) + d]; }
        __syncthreads();
        int dg = tid >> 6, cc = tid & 63;
        int c = part*64 + cc;
        float acc[B];
        #pragma unroll
        for (int b = 0; b < B; b++) acc[b] = 0.f;
        const float* wp = wkvb + (long)(h*(DN+DV) + dg*16)*KVLR + c;
        #pragma unroll
        for (int ds = 0; ds < 16; ds += 4){
            float w0 = wp[(long)(ds+0)*KVLR];
            float w1 = wp[(long)(ds+1)*KVLR];
            float w2 = wp[(long)(ds+2)*KVLR];
            float w3 = wp[(long)(ds+3)*KVLR];
            #pragma unroll
            for (int b = 0; b < B; b++){
                float4 q = *(const float4*)(&qn[b][dg*16 + ds]);
                acc[b] += q.x*w0 + q.y*w1 + q.z*w2 + q.w*w3;
            }
        }
        #pragma unroll
        for (int b = 0; b < B; b++) red[dg][b][cc] = acc[b];
        __syncthreads();
        for (int i = tid; i < B*64; i += 512){
            int b = i >> 6, c2 = i & 63;
            float s = 0.f;
            #pragma unroll
            for (int d = 0; d < 8; d++) s += red[d][b][c2];
            g_qfull[(b*H + h)*DHEAD + part*64 + c2] = s;
        }
    } else {
        if (tid < DR){
            int i = tid >> 1;
            float c = fcos[i], sn = fsin[i];
            for (int b = 0; b < B; b++){
                float xr = g_q[b*(H*(DN+DR)) + h*(DN+DR) + DN + 2*i];
                float xi = g_q[b*(H*(DN+DR)) + h*(DN+DR) + DN + 2*i + 1];
                g_qfull[(b*H + h)*DHEAD + KVLR + tid] =
                    (tid&1) ? (xr*sn + xi*c) : (xr*c - xi*sn);
            }
        }
    }
}

// ========== K5: persistent split-K attention (R11 configuration) ==========
// grid (16, 8), 512 threads. Each CTA: 16 chunks x 32 tokens, online softmax,
// cp.async double-buffered kv, tf32 MMA both GEMMs, Q frags hoisted.
#define SMF_KV0 0
#define SMF_KV1 18560
#define SMF_Q   37120
#define SMF_PR  46400
#define SMF_PS  48704
#define SMF_SC  49280
#define SM_TOTAL ((49280 + 16)*4)   // 197184 bytes

__device__ __forceinline__ void issue_chunk(
    const float* __restrict__ kvp, const float* __restrict__ pep,
    int b, int t0, uint32_t dstbase, const int* tk, const int* jk){
    #pragma unroll
    for (int k = 0; k < 9; k++){
        int tg = t0 + tk[k];
        int j = jk[k];
        const char* src;
        if (tg == T_PREFIX)
            src = (j < 128) ? (const char*)(g_kvn + b*KVLR) + j*16
                            : (const char*)(g_pen + b*DR) + (j-128)*16;
        else
            src = (j < 128) ? (const char*)(kvp + ((long)b*T_PREFIX + tg)*KVLR) + j*16
                            : (const char*)(pep + ((long)b*T_PREFIX + tg)*DR) + (j-128)*16;
        uint32_t dst = dstbase + (uint32_t)(tk[k]*2320 + j*16);
        asm volatile("cp.async.cg.shared.global [%0], [%1], 16;" :: "r"(dst), "l"(src));
    }
    asm volatile("cp.async.commit_group;" ::: "memory");
}

__global__ void __launch_bounds__(512, 1) k_attn(const float* __restrict__ kvp,
                                                 const float* __restrict__ pep){
    extern __shared__ float smf[];
    float* qs  = smf + SMF_Q;
    float* pr  = smf + SMF_PR;    // [4][16][36]
    float* ps  = smf + SMF_PS;    // [16][36]
    float* s_c = smf + SMF_SC;    // [16]
    int g = blockIdx.x, b = blockIdx.y, tid = threadIdx.x;
    int warp = tid >> 5, lane = tid & 31;
    int l4 = lane >> 2, lm4 = lane & 3;
    uint32_t sb = smem_u32(smf);

    int tk[9], jk[9];
    #pragma unroll
    for (int k = 0; k < 9; k++){ int idx = tid + 512*k; tk[k] = idx/144; jk[k] = idx%144; }

    issue_chunk(kvp, pep, b, g*NCPC*CHUNK, sb + SMF_KV0*4, tk, jk);

    {
        int h = warp;
        const float* qr = g_qfull + (long)(b*H + h)*DHEAD;
        #pragma unroll
        for (int i = 0; i < 5; i++){
            int j = lane + 32*i;
            if (j < 144)
                *(float4*)(qs + h*KSTR + 4*j) = *(const float4*)(qr + 4*j);
        }
    }
    __syncthreads();

    int tile_m = warp & 1, tile_n = (warp >> 1) & 1, kh = warp >> 2;
    uint32_t qf0[18], qf1[18];
    {
        const float* brow = qs + (tile_n*8 + l4)*KSTR + lm4;
        #pragma unroll
        for (int kc = 0; kc < 18; kc++){
            int k0 = kh*144 + kc*8;
            qf0[kc] = tf32_of(brow[k0]);
            qf1[kc] = tf32_of(brow[k0+4]);
        }
    }

    float m_run = -1e30f, l_run = 0.f;
    float acc[4][4];
    #pragma unroll
    for (int nt = 0; nt < 4; nt++)
        #pragma unroll
        for (int j = 0; j < 4; j++) acc[nt][j] = 0.f;

    for (int i = 0; i < NCPC; i++){
        if (i + 1 < NCPC){
            issue_chunk(kvp, pep, b, (g*NCPC + i + 1)*CHUNK,
                        sb + (((i+1)&1) ? SMF_KV1 : SMF_KV0)*4, tk, jk);
            asm volatile("cp.async.wait_group 1;" ::: "memory");
        } else {
            asm volatile("cp.async.wait_group 0;" ::: "memory");
        }
        __syncthreads();                        // (A)
        const float* kvs = smf + ((i&1) ? SMF_KV1 : SMF_KV0);

        // ---- scores: 2m x 2n x 4k-split; Q frags in registers ----
        {
            const float* arow0 = kvs + (tile_m*16 + l4)*KSTR + lm4;
            const float* arow1 = arow0 + 8*KSTR;
            float d0 = 0.f, d1 = 0.f, d2 = 0.f, d3 = 0.f;
            #pragma unroll
            for (int kc = 0; kc < 18; kc++){
                int k0 = kh*144 + kc*8;
                uint32_t a0 = tf32_of(arow0[k0]);
                uint32_t a1 = tf32_of(arow1[k0]);
                uint32_t a2 = tf32_of(arow0[k0+4]);
                uint32_t a3 = tf32_of(arow1[k0+4]);
                asm volatile("mma.sync.aligned.m16n8k8.row.col.f32.tf32.tf32.f32 "
                    "{%0,%1,%2,%3}, {%4,%5,%6,%7}, {%8,%9}, {%0,%1,%2,%3};"
                    : "+f"(d0),"+f"(d1),"+f"(d2),"+f"(d3)
                    : "r"(a0),"r"(a1),"r"(a2),"r"(a3), "r"(qf0[kc]),"r"(qf1[kc]));
            }
            int r0 = tile_m*16 + l4;
            int h0 = tile_n*8 + 2*lm4;
            pr[kh*576 + h0*PSTR + r0]           = d0;
            pr[kh*576 + (h0+1)*PSTR + r0]       = d1;
            pr[kh*576 + h0*PSTR + r0 + 8]       = d2;
            pr[kh*576 + (h0+1)*PSTR + r0 + 8]   = d3;
        }
        __syncthreads();                        // (B)

        // ---- online softmax: warp h, one token per lane ----
        {
            int h = warp;
            float v = (pr[h*PSTR + lane] + pr[576 + h*PSTR + lane]
                     + pr[1152 + h*PSTR + lane] + pr[1728 + h*PSTR + lane]) * SCALEF;
            float bm = v;
            #pragma unroll
            for (int o = 16; o; o >>= 1) bm = fmaxf(bm, __shfl_xor_sync(0xffffffffu, bm, o));
            float mn = fmaxf(m_run, bm);
            float corr = __expf(m_run - mn);
            float p = __expf(v - mn);
            float l = p;
            #pragma unroll
            for (int o = 16; o; o >>= 1) l += __shfl_xor_sync(0xffffffffu, l, o);
            l_run = l_run*corr + l;
            m_run = mn;
            ps[h*PSTR + lane] = p;
            if (lane == 0) s_c[h] = corr;
        }
        __syncthreads();                        // (C)

        // ---- accumulate via tf32 MMA: out[16h][32c per warp] += P @ KV ----
        {
            int n0 = warp*32;
            float corr0 = s_c[l4], corr1 = s_c[l4+8];
            #pragma unroll
            for (int nt = 0; nt < 4; nt++){
                acc[nt][0] *= corr0; acc[nt][1] *= corr0;
                acc[nt][2] *= corr1; acc[nt][3] *= corr1;
            }
            #pragma unroll
            for (int ks = 0; ks < 4; ks++){
                int k0 = ks*8;
                uint32_t a0 = tf32_of(ps[l4*PSTR + k0 + lm4]);
                uint32_t a1 = tf32_of(ps[(l4+8)*PSTR + k0 + lm4]);
                uint32_t a2 = tf32_of(ps[l4*PSTR + k0 + 4 + lm4]);
                uint32_t a3 = tf32_of(ps[(l4+8)*PSTR + k0 + 4 + lm4]);
                #pragma unroll
                for (int nt = 0; nt < 4; nt++){
                    int cn = n0 + nt*8 + l4;
                    uint32_t b0 = tf32_of(kvs[(k0 + lm4)*KSTR + cn]);
                    uint32_t b1 = tf32_of(kvs[(k0 + 4 + lm4)*KSTR + cn]);
                    asm volatile("mma.sync.aligned.m16n8k8.row.col.f32.tf32.tf32.f32 "
                        "{%0,%1,%2,%3}, {%4,%5,%6,%7}, {%8,%9}, {%0,%1,%2,%3};"
                        : "+f"(acc[nt][0]),"+f"(acc[nt][1]),"+f"(acc[nt][2]),"+f"(acc[nt][3])
                        : "r"(a0),"r"(a1),"r"(a2),"r"(a3), "r"(b0),"r"(b1));
                }
            }
        }
        // no end barrier (buffer reuse ordered by (A) of next iteration)
    }

    if (lane == 0){
        g_pm[(b*NCHUNK + g)*H + warp] = m_run;
        g_pl[(b*NCHUNK + g)*H + warp] = l_run;
    }
    {
        int n0 = warp*32;
        long base0 = ((long)(b*NCHUNK + g)*H + l4)*KVLR;
        long base1 = ((long)(b*NCHUNK + g)*H + l4 + 8)*KVLR;
        #pragma unroll
        for (int nt = 0; nt < 4; nt++){
            int c = n0 + nt*8 + 2*lm4;
            *(float2*)(g_pout + base0 + c) = make_float2(acc[nt][0], acc[nt][1]);
            *(float2*)(g_pout + base1 + c) = make_float2(acc[nt][2], acc[nt][3]);
        }
    }
}

// ========== K6: combine split-softmax partials + V projection ==========
__global__ void k_reduce(const float* __restrict__ wkvb){
    int h = blockIdx.x, b = blockIdx.y, tid = threadIdx.x;
    __shared__ float sm_m[NCHUNK], sm_l[NCHUNK], wk[NCHUNK];
    __shared__ float so[KVLR];
    if (tid < NCHUNK){
        sm_m[tid] = g_pm[(b*NCHUNK + tid)*H + h];
        sm_l[tid] = g_pl[(b*NCHUNK + tid)*H + h];
    }
    __syncthreads();
    if (tid < 32){
        float mv = (tid < NCHUNK) ? sm_m[tid] : -1e30f;
        float M = mv;
        #pragma unroll
        for (int o = 16; o; o >>= 1) M = fmaxf(M, __shfl_xor_sync(0xffffffffu, M, o));
        float e = __expf(mv - M);
        float L = (tid < NCHUNK) ? e*sm_l[tid] : 0.f;
        #pragma unroll
        for (int o = 16; o; o >>= 1) L += __shfl_xor_sync(0xffffffffu, L, o);
        if (tid < NCHUNK) wk[tid] = e / L;
    }
    __syncthreads();
    float out = 0.f;
    #pragma unroll
    for (int k = 0; k < NCHUNK; k++)
        out += wk[k]*g_pout[((long)(b*NCHUNK + k)*H + h)*KVLR + tid];
    so[tid] = out;
    __syncthreads();
    int d = tid >> 2, part = tid & 3;
    const float* wr = wkvb + (long)(h*(DN+DV) + DN + d)*KVLR + part*128;
    const float* sp = so + part*128;
    float s = 0.f;
    #pragma unroll 8
    for (int c = 0; c < 128; c++) s += sp[c]*wr[c];
    s += __shfl_xor_sync(0xffffffffu, s, 1);
    s += __shfl_xor_sync(0xffffffffu, s, 2);
    if (part == 0) g_out2[(b*H + h)*DV + d] = s;
}

// ========== K7: y = out2 @ wo^T + wo_b ==========
__global__ void k_proj_o(const float* __restrict__ wo, const float* __restrict__ wob,
                         float* __restrict__ out){
    extern __shared__ float xs[];
    int tid = threadIdx.x;
    for (int i = tid; i < B*DIM/4; i += blockDim.x)
        ((float4*)xs)[i] = ((const float4*)g_out2)[i];
    __syncthreads();
    int warp = tid >> 5, lane = tid & 31;
    int j = blockIdx.x * 8 + warp;
    const float* wr = wo + (long)j*DIM;
    float4 w[16];
    #pragma unroll
    for (int k = 0; k < 16; k++) w[k] = ((const float4*)wr)[lane + 32*k];
    float bias = wob[j];
    for (int b = 0; b < B; b++){
        const float4* xb = (const float4*)(xs + b*DIM);
        float s = 0.f;
        #pragma unroll
        for (int k = 0; k < 16; k++) s += dot4(w[k], xb[lane + 32*k]);
        #pragma unroll
        for (int o = 16; o; o >>= 1) s += __shfl_xor_sync(0xffffffffu, s, o);
        if (lane == 0) out[b*DIM + j] = s + bias;
    }
}

// ---------------- host launcher ----------------
extern "C" void kernel_launch(void* const* d_in, const int* in_sizes, int n_in,
                              void* d_out, int out_size){
    const float* x    = (const float*)d_in[0];
    const float* fcos = (const float*)d_in[2];
    const float* fsin = (const float*)d_in[3];
    const float* kvp  = (const float*)d_in[4];
    const float* pep  = (const float*)d_in[5];
    const float* wqa  = (const float*)d_in[6];
    const float* bqa  = (const float*)d_in[7];
    const float* qnw  = (const float*)d_in[8];
    const float* wqb  = (const float*)d_in[9];
    const float* bqb  = (const float*)d_in[10];
    const float* wkva = (const float*)d_in[11];
    const float* bkva = (const float*)d_in[12];
    const float* kvnw = (const float*)d_in[13];
    const float* wkvb = (const float*)d_in[14];
    const float* wo   = (const float*)d_in[15];
    const float* wob  = (const float*)d_in[16];
    float* out = (float*)d_out;

    const int SMEM_K1 = B*DIM*4;
    const int SMEM_K3 = B*QLR*4;
    const int SMEM_K7 = B*DIM*4;
    cudaFuncSetAttribute(k_proj_a,  cudaFuncAttributeMaxDynamicSharedMemorySize, SMEM_K1);
    cudaFuncSetAttribute(k_proj_qb, cudaFuncAttributeMaxDynamicSharedMemorySize, SMEM_K3);
    cudaFuncSetAttribute(k_attn,    cudaFuncAttributeMaxDynamicSharedMemorySize, SM_TOTAL);
    cudaFuncSetAttribute(k_proj_o,  cudaFuncAttributeMaxDynamicSharedMemorySize, SMEM_K7);

    k_proj_a<<<(QLR+KVLR+DR)/8, 256, SMEM_K1>>>(x, wqa, bqa, wkva, bkva);
    k_norm_rope<<<B, 512>>>(qnw, kvnw, fcos, fsin);
    k_proj_qb<<<(H*(DN+DR))/8, 256, SMEM_K3>>>(wqb, bqb);
    { dim3 g(H, 9); k_qfull<<<g, 512>>>(wkvb, fcos, fsin); }
    { dim3 g(NCHUNK, B); k_attn<<<g, 512, SM_TOTAL>>>(kvp, pep); }
    { dim3 g(H, B); k_reduce<<<g, 512>>>(wkvb); }
    k_proj_o<<<DIM/8, 256, SMEM_K7>>>(wo, wob, out);
}

// round 16
// speedup vs baseline: 1.1319x; 1.0304x over previous
#include <cuda_runtime.h>
#include <cuda_bf16.h>
#include <cstdint>

// ---------------- problem constants ----------------
#define B 8
#define H 16
#define DIM 2048
#define QLR 1536
#define KVLR 512
#define DN 128
#define DR 64
#define DV 128
#define T_TOT 8192
#define T_PREFIX 8191
#define NCHUNK 18          // chunk-groups (one partial per CTA)
#define TCHUNKS 256        // total 32-token chunks per batch
#define CHUNK 32           // tokens per chunk
#define DHEAD 576
#define KSTR 580           // fp32 row stride (≡4 mod 32 banks -> conflict-free frags)
#define PSTR 36            // probs row stride (≡4 mod 32)
#define SCALEF 0.07216878364870322f

typedef unsigned long long u64;

// ---------------- device scratch ----------------
__device__ float g_qa  [B*QLR];
__device__ float g_kvpe[B*(KVLR+DR)];
__device__ float g_qan [B*QLR];
__device__ float g_kvn [B*KVLR];
__device__ float g_pen [B*DR];
__device__ float g_q   [B*H*(DN+DR)];
__device__ float g_qfull[B*H*DHEAD];
__device__ float g_pm  [B*NCHUNK*H];
__device__ float g_pl  [B*NCHUNK*H];
__device__ float g_pout[B*NCHUNK*H*KVLR];
__device__ float g_out2[B*H*DV];

__device__ __forceinline__ uint32_t tf32_of(float f){
    uint32_t r; asm("cvt.rna.tf32.f32 %0, %1;" : "=r"(r) : "f"(f)); return r;
}
__device__ __forceinline__ uint32_t smem_u32(const void* p){
    uint32_t a;
    asm("{ .reg .u64 t; cvta.to.shared.u64 t, %1; cvt.u32.u64 %0, t; }" : "=r"(a) : "l"(p));
    return a;
}
__device__ __forceinline__ float dot4(float4 a, float4 b){
    return a.x*b.x + a.y*b.y + a.z*b.z + a.w*b.w;
}

// ========== K1: qa = x @ wq_a^T + b ; kvpe = x @ wkv_a^T + b ==========
__global__ void k_proj_a(const float* __restrict__ x,
                         const float* __restrict__ wqa, const float* __restrict__ bqa,
                         const float* __restrict__ wkva, const float* __restrict__ bkva){
    extern __shared__ float xs[];
    int tid = threadIdx.x;
    for (int i = tid; i < B*DIM/4; i += blockDim.x)
        ((float4*)xs)[i] = ((const float4*)x)[i];
    __syncthreads();
    int warp = tid >> 5, lane = tid & 31;
    int r = blockIdx.x * 8 + warp;
    if (r >= QLR + KVLR + DR) return;
    const float* wrow; float bias;
    if (r < QLR) { wrow = wqa + (long)r*DIM; bias = bqa[r]; }
    else         { wrow = wkva + (long)(r-QLR)*DIM; bias = bkva[r-QLR]; }
    float4 w[16];
    #pragma unroll
    for (int k = 0; k < 16; k++) w[k] = ((const float4*)wrow)[lane + 32*k];
    for (int b = 0; b < B; b++){
        const float4* xb = (const float4*)(xs + b*DIM);
        float s = 0.f;
        #pragma unroll
        for (int k = 0; k < 16; k++) s += dot4(w[k], xb[lane + 32*k]);
        #pragma unroll
        for (int o = 16; o; o >>= 1) s += __shfl_xor_sync(0xffffffffu, s, o);
        if (lane == 0){
            if (r < QLR) g_qa[b*QLR + r] = s + bias;
            else         g_kvpe[b*(KVLR+DR) + (r-QLR)] = s + bias;
        }
    }
}

// ========== K2: RMS-norm qa and kv; rope k_pe ==========
__global__ void k_norm_rope(const float* __restrict__ qnw, const float* __restrict__ kvnw,
                            const float* __restrict__ fcos, const float* __restrict__ fsin){
    int b = blockIdx.x, tid = threadIdx.x;
    __shared__ float red[16];
    __shared__ float sq, skv;
    float s = 0.f;
    for (int i = tid; i < QLR; i += 512){ float v = g_qa[b*QLR+i]; s += v*v; }
    #pragma unroll
    for (int o = 16; o; o >>= 1) s += __shfl_xor_sync(0xffffffffu, s, o);
    if ((tid&31) == 0) red[tid>>5] = s;
    __syncthreads();
    if (tid == 0){ float t=0; for (int i=0;i<16;i++) t += red[i];
                   sq = rsqrtf(t*(1.f/QLR) + 1e-6f); }
    __syncthreads();
    float s2 = 0.f;
    { float v = (tid < KVLR) ? g_kvpe[b*(KVLR+DR)+tid] : 0.f; s2 = v*v; }
    #pragma unroll
    for (int o = 16; o; o >>= 1) s2 += __shfl_xor_sync(0xffffffffu, s2, o);
    if ((tid&31) == 0) red[tid>>5] = s2;
    __syncthreads();
    if (tid == 0){ float t=0; for (int i=0;i<16;i++) t += red[i];
                   skv = rsqrtf(t*(1.f/KVLR) + 1e-6f); }
    __syncthreads();
    for (int i = tid; i < QLR; i += 512) g_qan[b*QLR+i] = g_qa[b*QLR+i]*qnw[i]*sq;
    if (tid < KVLR) g_kvn[b*KVLR+tid] = g_kvpe[b*(KVLR+DR)+tid]*kvnw[tid]*skv;
    if (tid < DR){
        int i = tid >> 1;
        float xr = g_kvpe[b*(KVLR+DR)+KVLR+2*i];
        float xi = g_kvpe[b*(KVLR+DR)+KVLR+2*i+1];
        float c = fcos[i], sn = fsin[i];
        g_pen[b*DR+tid] = (tid&1) ? (xr*sn + xi*c) : (xr*c - xi*sn);
    }
}

// ========== K3: q = qa_n @ wq_b^T + b ==========
__global__ void k_proj_qb(const float* __restrict__ wqb, const float* __restrict__ bqb){
    extern __shared__ float qs[];
    int tid = threadIdx.x;
    for (int i = tid; i < B*QLR/4; i += blockDim.x)
        ((float4*)qs)[i] = ((const float4*)g_qan)[i];
    __syncthreads();
    int warp = tid >> 5, lane = tid & 31;
    int r = blockIdx.x * 8 + warp;
    const float* wr = wqb + (long)r*QLR;
    float4 w[12];
    #pragma unroll
    for (int k = 0; k < 12; k++) w[k] = ((const float4*)wr)[lane + 32*k];
    float bias = bqb[r];
    for (int b = 0; b < B; b++){
        const float4* xb = (const float4*)(qs + b*QLR);
        float s = 0.f;
        #pragma unroll
        for (int k = 0; k < 12; k++) s += dot4(w[k], xb[lane + 32*k]);
        #pragma unroll
        for (int o = 16; o; o >>= 1) s += __shfl_xor_sync(0xffffffffu, s, o);
        if (lane == 0) g_q[b*(H*(DN+DR)) + r] = s + bias;
    }
}

// ========== K4: q_full = [q_nope @ wkv_b[:, :DN], rope(q_pe)] ==========
__global__ void k_qfull(const float* __restrict__ wkvb,
                        const float* __restrict__ fcos, const float* __restrict__ fsin){
    int h = blockIdx.x, part = blockIdx.y, tid = threadIdx.x;
    if (part < 8){
        __shared__ float qn[B][DN];
        __shared__ float red[8][B][65];
        for (int i = tid; i < B*DN; i += 512){ int b = i>>7, d = i&127;
            qn[b][d] = g_q[b*(H*(DN+DR)) + h*(DN+DR) + d]; }
        __syncthreads();
        int dg = tid >> 6, cc = tid & 63;
        int c = part*64 + cc;
        float acc[B];
        #pragma unroll
        for (int b = 0; b < B; b++) acc[b] = 0.f;
        const float* wp = wkvb + (long)(h*(DN+DV) + dg*16)*KVLR + c;
        #pragma unroll
        for (int ds = 0; ds < 16; ds += 4){
            float w0 = wp[(long)(ds+0)*KVLR];
            float w1 = wp[(long)(ds+1)*KVLR];
            float w2 = wp[(long)(ds+2)*KVLR];
            float w3 = wp[(long)(ds+3)*KVLR];
            #pragma unroll
            for (int b = 0; b < B; b++){
                float4 q = *(const float4*)(&qn[b][dg*16 + ds]);
                acc[b] += q.x*w0 + q.y*w1 + q.z*w2 + q.w*w3;
            }
        }
        #pragma unroll
        for (int b = 0; b < B; b++) red[dg][b][cc] = acc[b];
        __syncthreads();
        for (int i = tid; i < B*64; i += 512){
            int b = i >> 6, c2 = i & 63;
            float s = 0.f;
            #pragma unroll
            for (int d = 0; d < 8; d++) s += red[d][b][c2];
            g_qfull[(b*H + h)*DHEAD + part*64 + c2] = s;
        }
    } else {
        if (tid < DR){
            int i = tid >> 1;
            float c = fcos[i], sn = fsin[i];
            for (int b = 0; b < B; b++){
                float xr = g_q[b*(H*(DN+DR)) + h*(DN+DR) + DN + 2*i];
                float xi = g_q[b*(H*(DN+DR)) + h*(DN+DR) + DN + 2*i + 1];
                g_qfull[(b*H + h)*DHEAD + KVLR + tid] =
                    (tid&1) ? (xr*sn + xi*c) : (xr*c - xi*sn);
            }
        }
    }
}

// ========== K5: persistent split-K attention ==========
// grid (18, 8), 512 threads. CTA g handles chunks [g*256/18, (g+1)*256/18).
// cp.async double-buffered kv, tf32 MMA both GEMMs, raw-bit tf32 operands from smem.
#define SMF_KV0 0
#define SMF_KV1 18560
#define SMF_Q   37120
#define SMF_PR  46400
#define SMF_PS  48704
#define SMF_SC  49280
#define SM_TOTAL ((49280 + 16)*4)   // 197184 bytes

__device__ __forceinline__ void issue_chunk(
    const float* __restrict__ kvp, const float* __restrict__ pep,
    int b, int t0, uint32_t dstbase, const int* tk, const int* jk){
    #pragma unroll
    for (int k = 0; k < 9; k++){
        int tg = t0 + tk[k];
        int j = jk[k];
        const char* src;
        if (tg == T_PREFIX)
            src = (j < 128) ? (const char*)(g_kvn + b*KVLR) + j*16
                            : (const char*)(g_pen + b*DR) + (j-128)*16;
        else
            src = (j < 128) ? (const char*)(kvp + ((long)b*T_PREFIX + tg)*KVLR) + j*16
                            : (const char*)(pep + ((long)b*T_PREFIX + tg)*DR) + (j-128)*16;
        uint32_t dst = dstbase + (uint32_t)(tk[k]*2320 + j*16);
        asm volatile("cp.async.cg.shared.global [%0], [%1], 16;" :: "r"(dst), "l"(src));
    }
    asm volatile("cp.async.commit_group;" ::: "memory");
}

__global__ void __launch_bounds__(512, 1) k_attn(const float* __restrict__ kvp,
                                                 const float* __restrict__ pep){
    extern __shared__ float smf[];
    float* qs  = smf + SMF_Q;
    float* pr  = smf + SMF_PR;    // [4][16][36]
    float* ps  = smf + SMF_PS;    // [16][36]
    float* s_c = smf + SMF_SC;    // [16]
    int g = blockIdx.x, b = blockIdx.y, tid = threadIdx.x;
    int warp = tid >> 5, lane = tid & 31;
    int l4 = lane >> 2, lm4 = lane & 3;
    uint32_t sb = smem_u32(smf);
    const uint32_t* kvu;

    int cs = (g*TCHUNKS)/NCHUNK, ce = ((g+1)*TCHUNKS)/NCHUNK;

    int tk[9], jk[9];
    #pragma unroll
    for (int k = 0; k < 9; k++){ int idx = tid + 512*k; tk[k] = idx/144; jk[k] = idx%144; }

    issue_chunk(kvp, pep, b, cs*CHUNK, sb + SMF_KV0*4, tk, jk);

    {
        int h = warp;
        const float* qr = g_qfull + (long)(b*H + h)*DHEAD;
        #pragma unroll
        for (int i = 0; i < 5; i++){
            int j = lane + 32*i;
            if (j < 144)
                *(float4*)(qs + h*KSTR + 4*j) = *(const float4*)(qr + 4*j);
        }
    }
    __syncthreads();

    int tile_m = warp & 1, tile_n = (warp >> 1) & 1, kh = warp >> 2;
    uint32_t qf0[18], qf1[18];
    {
        const float* brow = qs + (tile_n*8 + l4)*KSTR + lm4;
        #pragma unroll
        for (int kc = 0; kc < 18; kc++){
            int k0 = kh*144 + kc*8;
            qf0[kc] = tf32_of(brow[k0]);
            qf1[kc] = tf32_of(brow[k0+4]);
        }
    }

    float m_run = -1e30f, l_run = 0.f;
    float acc[4][4];
    #pragma unroll
    for (int nt = 0; nt < 4; nt++)
        #pragma unroll
        for (int j = 0; j < 4; j++) acc[nt][j] = 0.f;

    for (int i = cs; i < ce; i++){
        int li = i - cs;
        if (i + 1 < ce){
            issue_chunk(kvp, pep, b, (i + 1)*CHUNK,
                        sb + (((li+1)&1) ? SMF_KV1 : SMF_KV0)*4, tk, jk);
            asm volatile("cp.async.wait_group 1;" ::: "memory");
        } else {
            asm volatile("cp.async.wait_group 0;" ::: "memory");
        }
        __syncthreads();                        // (A)
        kvu = (const uint32_t*)(smf + ((li&1) ? SMF_KV1 : SMF_KV0));

        // ---- scores: 2m x 2n x 4k-split; raw-bit tf32 kv operands ----
        {
            const uint32_t* arow0 = kvu + (tile_m*16 + l4)*KSTR + lm4;
            const uint32_t* arow1 = arow0 + 8*KSTR;
            float d0 = 0.f, d1 = 0.f, d2 = 0.f, d3 = 0.f;
            #pragma unroll
            for (int kc = 0; kc < 18; kc++){
                int k0 = kh*144 + kc*8;
                uint32_t a0 = arow0[k0];
                uint32_t a1 = arow1[k0];
                uint32_t a2 = arow0[k0+4];
                uint32_t a3 = arow1[k0+4];
                asm volatile("mma.sync.aligned.m16n8k8.row.col.f32.tf32.tf32.f32 "
                    "{%0,%1,%2,%3}, {%4,%5,%6,%7}, {%8,%9}, {%0,%1,%2,%3};"
                    : "+f"(d0),"+f"(d1),"+f"(d2),"+f"(d3)
                    : "r"(a0),"r"(a1),"r"(a2),"r"(a3), "r"(qf0[kc]),"r"(qf1[kc]));
            }
            int r0 = tile_m*16 + l4;
            int h0 = tile_n*8 + 2*lm4;
            pr[kh*576 + h0*PSTR + r0]           = d0;
            pr[kh*576 + (h0+1)*PSTR + r0]       = d1;
            pr[kh*576 + h0*PSTR + r0 + 8]       = d2;
            pr[kh*576 + (h0+1)*PSTR + r0 + 8]   = d3;
        }
        __syncthreads();                        // (B)

        // ---- online softmax: warp h, one token per lane ----
        {
            int h = warp;
            float v = (pr[h*PSTR + lane] + pr[576 + h*PSTR + lane]
                     + pr[1152 + h*PSTR + lane] + pr[1728 + h*PSTR + lane]) * SCALEF;
            float bm = v;
            #pragma unroll
            for (int o = 16; o; o >>= 1) bm = fmaxf(bm, __shfl_xor_sync(0xffffffffu, bm, o));
            float mn = fmaxf(m_run, bm);
            float corr = __expf(m_run - mn);
            float p = __expf(v - mn);
            float l = p;
            #pragma unroll
            for (int o = 16; o; o >>= 1) l += __shfl_xor_sync(0xffffffffu, l, o);
            l_run = l_run*corr + l;
            m_run = mn;
            ps[h*PSTR + lane] = p;
            if (lane == 0) s_c[h] = corr;
        }
        __syncthreads();                        // (C)

        // ---- accumulate via tf32 MMA (raw-bit operands) ----
        {
            const uint32_t* psu = (const uint32_t*)ps;
            int n0 = warp*32;
            float corr0 = s_c[l4], corr1 = s_c[l4+8];
            #pragma unroll
            for (int nt = 0; nt < 4; nt++){
                acc[nt][0] *= corr0; acc[nt][1] *= corr0;
                acc[nt][2] *= corr1; acc[nt][3] *= corr1;
            }
            #pragma unroll
            for (int ks = 0; ks < 4; ks++){
                int k0 = ks*8;
                uint32_t a0 = psu[l4*PSTR + k0 + lm4];
                uint32_t a1 = psu[(l4+8)*PSTR + k0 + lm4];
                uint32_t a2 = psu[l4*PSTR + k0 + 4 + lm4];
                uint32_t a3 = psu[(l4+8)*PSTR + k0 + 4 + lm4];
                #pragma unroll
                for (int nt = 0; nt < 4; nt++){
                    int cn = n0 + nt*8 + l4;
                    uint32_t b0 = kvu[(k0 + lm4)*KSTR + cn];
                    uint32_t b1 = kvu[(k0 + 4 + lm4)*KSTR + cn];
                    asm volatile("mma.sync.aligned.m16n8k8.row.col.f32.tf32.tf32.f32 "
                        "{%0,%1,%2,%3}, {%4,%5,%6,%7}, {%8,%9}, {%0,%1,%2,%3};"
                        : "+f"(acc[nt][0]),"+f"(acc[nt][1]),"+f"(acc[nt][2]),"+f"(acc[nt][3])
                        : "r"(a0),"r"(a1),"r"(a2),"r"(a3), "r"(b0),"r"(b1));
                }
            }
        }
        // no end barrier (buffer reuse ordered by (A) of next iteration)
    }

    if (lane == 0){
        g_pm[(b*NCHUNK + g)*H + warp] = m_run;
        g_pl[(b*NCHUNK + g)*H + warp] = l_run;
    }
    {
        int n0 = warp*32;
        long base0 = ((long)(b*NCHUNK + g)*H + l4)*KVLR;
        long base1 = ((long)(b*NCHUNK + g)*H + l4 + 8)*KVLR;
        #pragma unroll
        for (int nt = 0; nt < 4; nt++){
            int c = n0 + nt*8 + 2*lm4;
            *(float2*)(g_pout + base0 + c) = make_float2(acc[nt][0], acc[nt][1]);
            *(float2*)(g_pout + base1 + c) = make_float2(acc[nt][2], acc[nt][3]);
        }
    }
}

// ========== K6: combine split-softmax partials + V projection ==========
__global__ void k_reduce(const float* __restrict__ wkvb){
    int h = blockIdx.x, b = blockIdx.y, tid = threadIdx.x;
    __shared__ float sm_m[NCHUNK], sm_l[NCHUNK], wk[NCHUNK];
    __shared__ float so[KVLR];
    if (tid < NCHUNK){
        sm_m[tid] = g_pm[(b*NCHUNK + tid)*H + h];
        sm_l[tid] = g_pl[(b*NCHUNK + tid)*H + h];
    }
    __syncthreads();
    if (tid < 32){
        float mv = (tid < NCHUNK) ? sm_m[tid] : -1e30f;
        float M = mv;
        #pragma unroll
        for (int o = 16; o; o >>= 1) M = fmaxf(M, __shfl_xor_sync(0xffffffffu, M, o));
        float e = __expf(mv - M);
        float L = (tid < NCHUNK) ? e*sm_l[tid] : 0.f;
        #pragma unroll
        for (int o = 16; o; o >>= 1) L += __shfl_xor_sync(0xffffffffu, L, o);
        if (tid < NCHUNK) wk[tid] = e / L;
    }
    __syncthreads();
    float out = 0.f;
    #pragma unroll 2
    for (int k = 0; k < NCHUNK; k++)
        out += wk[k]*g_pout[((long)(b*NCHUNK + k)*H + h)*KVLR + tid];
    so[tid] = out;
    __syncthreads();
    int d = tid >> 2, part = tid & 3;
    const float* wr = wkvb + (long)(h*(DN+DV) + DN + d)*KVLR + part*128;
    const float* sp = so + part*128;
    float s = 0.f;
    #pragma unroll 8
    for (int c = 0; c < 128; c++) s += sp[c]*wr[c];
    s += __shfl_xor_sync(0xffffffffu, s, 1);
    s += __shfl_xor_sync(0xffffffffu, s, 2);
    if (part == 0) g_out2[(b*H + h)*DV + d] = s;
}

// ========== K7: y = out2 @ wo^T + wo_b ==========
__global__ void k_proj_o(const float* __restrict__ wo, const float* __restrict__ wob,
                         float* __restrict__ out){
    extern __shared__ float xs[];
    int tid = threadIdx.x;
    for (int i = tid; i < B*DIM/4; i += blockDim.x)
        ((float4*)xs)[i] = ((const float4*)g_out2)[i];
    __syncthreads();
    int warp = tid >> 5, lane = tid & 31;
    int j = blockIdx.x * 8 + warp;
    const float* wr = wo + (long)j*DIM;
    float4 w[16];
    #pragma unroll
    for (int k = 0; k < 16; k++) w[k] = ((const float4*)wr)[lane + 32*k];
    float bias = wob[j];
    for (int b = 0; b < B; b++){
        const float4* xb = (const float4*)(xs + b*DIM);
        float s = 0.f;
        #pragma unroll
        for (int k = 0; k < 16; k++) s += dot4(w[k], xb[lane + 32*k]);
        #pragma unroll
        for (int o = 16; o; o >>= 1) s += __shfl_xor_sync(0xffffffffu, s, o);
        if (lane == 0) out[b*DIM + j] = s + bias;
    }
}

// ---------------- host launcher ----------------
extern "C" void kernel_launch(void* const* d_in, const int* in_sizes, int n_in,
                              void* d_out, int out_size){
    const float* x    = (const float*)d_in[0];
    const float* fcos = (const float*)d_in[2];
    const float* fsin = (const float*)d_in[3];
    const float* kvp  = (const float*)d_in[4];
    const float* pep  = (const float*)d_in[5];
    const float* wqa  = (const float*)d_in[6];
    const float* bqa  = (const float*)d_in[7];
    const float* qnw  = (const float*)d_in[8];
    const float* wqb  = (const float*)d_in[9];
    const float* bqb  = (const float*)d_in[10];
    const float* wkva = (const float*)d_in[11];
    const float* bkva = (const float*)d_in[12];
    const float* kvnw = (const float*)d_in[13];
    const float* wkvb = (const float*)d_in[14];
    const float* wo   = (const float*)d_in[15];
    const float* wob  = (const float*)d_in[16];
    float* out = (float*)d_out;

    const int SMEM_K1 = B*DIM*4;
    const int SMEM_K3 = B*QLR*4;
    const int SMEM_K7 = B*DIM*4;
    cudaFuncSetAttribute(k_proj_a,  cudaFuncAttributeMaxDynamicSharedMemorySize, SMEM_K1);
    cudaFuncSetAttribute(k_proj_qb, cudaFuncAttributeMaxDynamicSharedMemorySize, SMEM_K3);
    cudaFuncSetAttribute(k_attn,    cudaFuncAttributeMaxDynamicSharedMemorySize, SM_TOTAL);
    cudaFuncSetAttribute(k_proj_o,  cudaFuncAttributeMaxDynamicSharedMemorySize, SMEM_K7);

    k_proj_a<<<(QLR+KVLR+DR)/8, 256, SMEM_K1>>>(x, wqa, bqa, wkva, bkva);
    k_norm_rope<<<B, 512>>>(qnw, kvnw, fcos, fsin);
    k_proj_qb<<<(H*(DN+DR))/8, 256, SMEM_K3>>>(wqb, bqb);
    { dim3 g(H, 9); k_qfull<<<g, 512>>>(wkvb, fcos, fsin); }
    { dim3 g(NCHUNK, B); k_attn<<<g, 512, SM_TOTAL>>>(kvp, pep); }
    { dim3 g(H, B); k_reduce<<<g, 512>>>(wkvb); }
    k_proj_o<<<DIM/8, 256, SMEM_K7>>>(wo, wob, out);
}